// round 16
// baseline (speedup 1.0000x reference)
#include <cuda_runtime.h>
#include <cuda_bf16.h>
#include <cstdint>
#include <math.h>

// ============================================================
// DocAttention via Gram-matrix restructure (sm_103 family-safe mma.sync).
//   M = Wq @ Wk^T ;  S_b = cls_b @ M @ cls_b^T
//   logits[b,x] = sum_{a!=x, m_a=1} S_b[x,a] (+ exact bias via u,v,c0)
//   out = softmax(logits + (1-m)*-1e5)
// K1: converts (cls, W) + fused u,v GEMVs + c0
// K2: MT = Wk @ Wq^T, split-K=2 (128 CTAs x 8 iters), pair-combine hadd2
// K3: quad-batch (128 cls rows/CTA) x e-slice x d-split: P-GEMM (8 iters),
//     batch-sequential S-MMA, per-batch last-CTA softmax
// ============================================================

__device__ __forceinline__ uint32_t smem_u32(const void* p) {
    uint32_t a;
    asm("{ .reg .u64 t; cvta.to.shared.u64 t, %1; cvt.u32.u64 %0, t; }"
        : "=r"(a) : "l"(p));
    return a;
}

// ---------------- scratch ----------------
__device__ __align__(16) __nv_bfloat16 g_A[1024 * 1024];      // cls bf16 [row][d]
__device__ __align__(16) __nv_bfloat16 g_Wbf[2 * 1024 * 1024];// Wq | Wk bf16 [d][h]
__device__ __align__(16) __nv_bfloat16 g_MT0[1024 * 1024];    // MT partial ks=0
__device__ __align__(16) __nv_bfloat16 g_MT1[1024 * 1024];    // MT partial ks=1
__device__ __align__(16) __nv_bfloat16 g_MT[1024 * 1024];     // MT[e][d] bf16 combined
__device__ float g_u[1024];
__device__ float g_v[1024];
__device__ float g_c0;
__device__ float g_part[32 * 16 * 1024];                       // [b][slice*2+ks][1024]
__device__ int   g_bctr[32];
__device__ int   g_tilectr[64];

// ================= K1: converts + fused GEMVs (unchanged, proven 8.1us) ====
__global__ __launch_bounds__(256) void k1_convert(const float* __restrict__ enc,
                                                  const float* __restrict__ wq,
                                                  const float* __restrict__ wk,
                                                  const float* __restrict__ bq,
                                                  const float* __restrict__ bk) {
    const int blk = blockIdx.x;
    const int tid = threadIdx.x, warp = tid >> 5, lane = tid & 31;

    if (blk < 128) {
        const int row = blk * 8 + warp;
        const float4* __restrict__ src =
            reinterpret_cast<const float4*>(enc + (size_t)row * 131072);
        uint2* __restrict__ dst = reinterpret_cast<uint2*>(g_A + (size_t)row * 1024);
        float4 v[8];
        #pragma unroll
        for (int i = 0; i < 8; i++) v[i] = src[lane + 32 * i];
        #pragma unroll
        for (int i = 0; i < 8; i++) {
            __nv_bfloat16 h[4];
            h[0] = __float2bfloat16(v[i].x);
            h[1] = __float2bfloat16(v[i].y);
            h[2] = __float2bfloat16(v[i].z);
            h[3] = __float2bfloat16(v[i].w);
            dst[lane + 32 * i] = *reinterpret_cast<uint2*>(h);
        }
        return;
    }
    if (blk < 384) {
        __shared__ float red[64];
        const int idx = blk - 128;
        const bool isU = (idx < 128);
        const int rowbase = (isU ? idx : idx - 128) * 8;
        const float* __restrict__ src =
            isU ? (wq + (size_t)idx * 8192) : (wk + (size_t)(idx - 128) * 8192);
        const float* __restrict__ bvec = isU ? bk : bq;
        float* __restrict__ dstv = isU ? g_u : g_v;

        const float4* __restrict__ s4 = reinterpret_cast<const float4*>(src);
        uint2* __restrict__ d2 = reinterpret_cast<uint2*>(g_Wbf + (size_t)idx * 8192);
        float4 v[8];
        #pragma unroll
        for (int i = 0; i < 8; i++) v[i] = s4[tid + 256 * i];
        #pragma unroll
        for (int i = 0; i < 8; i++) {
            __nv_bfloat16 h[4];
            h[0] = __float2bfloat16(v[i].x);
            h[1] = __float2bfloat16(v[i].y);
            h[2] = __float2bfloat16(v[i].z);
            h[3] = __float2bfloat16(v[i].w);
            d2[tid + 256 * i] = *reinterpret_cast<uint2*>(h);
        }
        const float4 bv = reinterpret_cast<const float4*>(bvec)[tid];
        float p[8];
        #pragma unroll
        for (int i = 0; i < 8; i++) {
            p[i] = v[i].x * bv.x;
            p[i] = fmaf(v[i].y, bv.y, p[i]);
            p[i] = fmaf(v[i].z, bv.z, p[i]);
            p[i] = fmaf(v[i].w, bv.w, p[i]);
        }
        #pragma unroll
        for (int i = 0; i < 8; i++)
            #pragma unroll
            for (int o = 16; o > 0; o >>= 1)
                p[i] += __shfl_xor_sync(0xFFFFFFFFu, p[i], o);
        if (lane == 0)
            #pragma unroll
            for (int i = 0; i < 8; i++) red[warp * 8 + i] = p[i];
        __syncthreads();
        if (tid < 8) {
            float s = 0.f;
            #pragma unroll
            for (int w = 0; w < 8; w++) s += red[w * 8 + tid];
            dstv[rowbase + tid] = s;
        }
        return;
    }
    if (warp == 0) {
        float acc = 0.f;
        #pragma unroll
        for (int j = 0; j < 32; j++) {
            const int h = lane + j * 32;
            acc = fmaf(bq[h], bk[h], acc);
        }
        #pragma unroll
        for (int o = 16; o > 0; o >>= 1)
            acc += __shfl_xor_sync(0xFFFFFFFFu, acc, o);
        if (lane == 0) g_c0 = acc;
    }
}

// ================= K2: MT GEMM, split-K=2 + pair combine ====================
// grid (8 dt, 8 et, 2 ks) = 128 CTAs, 8 K-chunks each.
#define BK 64
#define STG2 32768
#define NST 4

__global__ __launch_bounds__(256, 1)
void k2_mt_gemm() {
    extern __shared__ __align__(1024) char smem[];
    const uint32_t base = smem_u32(smem);
    const int tid = threadIdx.x, warp = tid >> 5, lane = tid & 31;
    const int dBase = blockIdx.x * 128;
    const int eBase = blockIdx.y * 128;
    const int ks = blockIdx.z;
    const int kOff = ks * 8;
    const int mw = (warp & 1) * 64;
    const int nw = (warp >> 1) * 32;
    const int lj = lane >> 3, li = lane & 7;

    float c[4][4][4];
    #pragma unroll
    for (int i = 0; i < 4; i++)
        #pragma unroll
        for (int j = 0; j < 4; j++)
            #pragma unroll
            for (int r = 0; r < 4; r++) c[i][j][r] = 0.f;

    const __nv_bfloat16* __restrict__ Wk_ = g_Wbf + 1048576;
    const __nv_bfloat16* __restrict__ Wq_ = g_Wbf;

    auto issue = [&](int kb) {
        const int stage = kb & (NST - 1);
        const uint32_t sA = base + (uint32_t)stage * STG2;
        const uint32_t sB = sA + 16384;
        const int k0 = (kOff + kb) * BK;
        #pragma unroll
        for (int i = 0; i < 4; i++) {
            const int idx = i * 256 + tid;
            const int row = idx >> 3, ch = idx & 7;
            const uint32_t swz = (uint32_t)((ch ^ (row & 7)) << 4);
            const __nv_bfloat16* gA = Wk_ + (size_t)(eBase + row) * 1024 + k0 + ch * 8;
            const __nv_bfloat16* gB = Wq_ + (size_t)(dBase + row) * 1024 + k0 + ch * 8;
            asm volatile("cp.async.cg.shared.global [%0], [%1], 16;"
                         :: "r"(sA + (uint32_t)row * 128 + swz), "l"(gA));
            asm volatile("cp.async.cg.shared.global [%0], [%1], 16;"
                         :: "r"(sB + (uint32_t)row * 128 + swz), "l"(gB));
        }
        asm volatile("cp.async.commit_group;");
    };

    auto compute = [&](int stage) {
        const uint32_t sA = base + (uint32_t)stage * STG2;
        const uint32_t sB = sA + 16384;
        #pragma unroll
        for (int kc = 0; kc < 4; kc++) {
            uint32_t a[4][4];
            #pragma unroll
            for (int mt = 0; mt < 4; mt++) {
                const int row = mw + mt * 16 + ((lj & 1) << 3) + li;
                const int ch = kc * 2 + (lj >> 1);
                asm volatile("ldmatrix.sync.aligned.m8n8.x4.shared.b16 "
                             "{%0,%1,%2,%3}, [%4];"
                             : "=r"(a[mt][0]), "=r"(a[mt][1]),
                               "=r"(a[mt][2]), "=r"(a[mt][3])
                             : "r"(sA + (uint32_t)(row * 128 + ((ch ^ (row & 7)) << 4))));
            }
            uint32_t b[2][4];
            #pragma unroll
            for (int nh = 0; nh < 2; nh++) {
                const int row = nw + nh * 16 + ((lj >> 1) << 3) + li;
                const int ch = kc * 2 + (lj & 1);
                asm volatile("ldmatrix.sync.aligned.m8n8.x4.shared.b16 "
                             "{%0,%1,%2,%3}, [%4];"
                             : "=r"(b[nh][0]), "=r"(b[nh][1]),
                               "=r"(b[nh][2]), "=r"(b[nh][3])
                             : "r"(sB + (uint32_t)(row * 128 + ((ch ^ (row & 7)) << 4))));
            }
            #pragma unroll
            for (int mt = 0; mt < 4; mt++)
                #pragma unroll
                for (int nt = 0; nt < 4; nt++) {
                    asm volatile(
                        "mma.sync.aligned.m16n8k16.row.col.f32.bf16.bf16.f32 "
                        "{%0,%1,%2,%3}, {%4,%5,%6,%7}, {%8,%9}, {%0,%1,%2,%3};"
                        : "+f"(c[mt][nt][0]), "+f"(c[mt][nt][1]),
                          "+f"(c[mt][nt][2]), "+f"(c[mt][nt][3])
                        : "r"(a[mt][0]), "r"(a[mt][1]), "r"(a[mt][2]), "r"(a[mt][3]),
                          "r"(b[nt >> 1][(nt & 1) * 2]),
                          "r"(b[nt >> 1][(nt & 1) * 2 + 1]));
                }
        }
    };

    issue(0); issue(1); issue(2);
    for (int kb = 0; kb < 8; kb++) {
        if (kb < 6)       asm volatile("cp.async.wait_group 2;");
        else if (kb == 6) asm volatile("cp.async.wait_group 1;");
        else              asm volatile("cp.async.wait_group 0;");
        __syncthreads();
        if (kb + 3 < 8) issue(kb + 3);
        compute(kb & (NST - 1));
    }

    // write partial
    __nv_bfloat16* __restrict__ dst = ks ? g_MT1 : g_MT0;
    #pragma unroll
    for (int mt = 0; mt < 4; mt++)
        #pragma unroll
        for (int half = 0; half < 2; half++) {
            const int e = eBase + mw + mt * 16 + (lane >> 2) + half * 8;
            #pragma unroll
            for (int nt = 0; nt < 4; nt++) {
                const int d = dBase + nw + nt * 8 + (lane & 3) * 2;
                __nv_bfloat162 hv;
                hv.x = __float2bfloat16(c[mt][nt][half * 2 + 0]);
                hv.y = __float2bfloat16(c[mt][nt][half * 2 + 1]);
                *reinterpret_cast<__nv_bfloat162*>(&dst[(size_t)e * 1024 + d]) = hv;
            }
        }

    // second CTA of the pair combines the tile
    __shared__ int doComb;
    __syncthreads();
    if (tid == 0) {
        __threadfence();
        doComb = (atomicAdd(&g_tilectr[blockIdx.y * 8 + blockIdx.x], 1) == 1);
    }
    __syncthreads();
    if (!doComb) return;
    if (tid == 0) g_tilectr[blockIdx.y * 8 + blockIdx.x] = 0;
    __threadfence();

    #pragma unroll
    for (int i = 0; i < 8; i++) {
        const int lin = tid + i * 256;        // 2048 uint4 per 128x128 tile
        const int row = lin >> 4, chn = lin & 15;
        const size_t off = (size_t)(eBase + row) * 1024 + dBase + chn * 8;
        uint4 u0 = *reinterpret_cast<const uint4*>(g_MT0 + off);
        uint4 u1 = *reinterpret_cast<const uint4*>(g_MT1 + off);
        const __nv_bfloat162* p0 = reinterpret_cast<const __nv_bfloat162*>(&u0);
        const __nv_bfloat162* p1 = reinterpret_cast<const __nv_bfloat162*>(&u1);
        uint4 r;
        __nv_bfloat162* pr = reinterpret_cast<__nv_bfloat162*>(&r);
        #pragma unroll
        for (int j = 0; j < 4; j++) pr[j] = __hadd2(p0[j], p1[j]);
        *reinterpret_cast<uint4*>(g_MT + off) = r;
    }
}

// ================= K3: quad-batch fused P-GEMM + S-MMA + softmax ============
// grid (8 slices, 8 quads, 2 ks). CTA: 128 cls rows (4 batches) x 128 e-slice,
// d-range [ks*512, ks*512+512). smem: 4 x 32KB stages; post-mainloop overlay:
//   P [0,32K), clsB [32K,64K), S8 [64K,96K).
#define STG3 32768
#define K3_SMEM (4 * STG3)

__global__ __launch_bounds__(256, 1)
void k3_fused(const int* __restrict__ mask, float* __restrict__ out) {
    extern __shared__ __align__(1024) char smem[];
    const uint32_t base = smem_u32(smem);
    const int tid = threadIdx.x, warp = tid >> 5, lane = tid & 31;
    const int slice = blockIdx.x;
    const int q = blockIdx.y;
    const int ks = blockIdx.z;
    const int n0e = slice * 128;
    const int kOff = ks * 8;
    const int mw = (warp & 1) * 64;
    const int nw = (warp >> 1) * 32;
    const int lj = lane >> 3, li = lane & 7;

    float c[4][4][4];
    #pragma unroll
    for (int i = 0; i < 4; i++)
        #pragma unroll
        for (int j = 0; j < 4; j++)
            #pragma unroll
            for (int r = 0; r < 4; r++) c[i][j][r] = 0.f;

    auto issue = [&](int kb) {
        const int stage = kb & (NST - 1);
        const uint32_t sA = base + (uint32_t)stage * STG3;
        const uint32_t sB = sA + 16384;
        const int k0 = (kOff + kb) * BK;
        #pragma unroll
        for (int i = 0; i < 4; i++) {
            const int idx = i * 256 + tid;
            const int row = idx >> 3, ch = idx & 7;
            const uint32_t swz = (uint32_t)((ch ^ (row & 7)) << 4);
            const __nv_bfloat16* gA = g_A + (size_t)(q * 128 + row) * 1024 + k0 + ch * 8;
            const __nv_bfloat16* gB = g_MT + (size_t)(n0e + row) * 1024 + k0 + ch * 8;
            asm volatile("cp.async.cg.shared.global [%0], [%1], 16;"
                         :: "r"(sA + (uint32_t)row * 128 + swz), "l"(gA));
            asm volatile("cp.async.cg.shared.global [%0], [%1], 16;"
                         :: "r"(sB + (uint32_t)row * 128 + swz), "l"(gB));
        }
        asm volatile("cp.async.commit_group;");
    };

    auto compute = [&](int stage) {
        const uint32_t sA = base + (uint32_t)stage * STG3;
        const uint32_t sB = sA + 16384;
        #pragma unroll
        for (int kc = 0; kc < 4; kc++) {
            uint32_t a[4][4];
            #pragma unroll
            for (int mt = 0; mt < 4; mt++) {
                const int row = mw + mt * 16 + ((lj & 1) << 3) + li;
                const int ch = kc * 2 + (lj >> 1);
                asm volatile("ldmatrix.sync.aligned.m8n8.x4.shared.b16 "
                             "{%0,%1,%2,%3}, [%4];"
                             : "=r"(a[mt][0]), "=r"(a[mt][1]),
                               "=r"(a[mt][2]), "=r"(a[mt][3])
                             : "r"(sA + (uint32_t)(row * 128 + ((ch ^ (row & 7)) << 4))));
            }
            uint32_t b[2][4];
            #pragma unroll
            for (int nh = 0; nh < 2; nh++) {
                const int row = nw + nh * 16 + ((lj >> 1) << 3) + li;
                const int ch = kc * 2 + (lj & 1);
                asm volatile("ldmatrix.sync.aligned.m8n8.x4.shared.b16 "
                             "{%0,%1,%2,%3}, [%4];"
                             : "=r"(b[nh][0]), "=r"(b[nh][1]),
                               "=r"(b[nh][2]), "=r"(b[nh][3])
                             : "r"(sB + (uint32_t)(row * 128 + ((ch ^ (row & 7)) << 4))));
            }
            #pragma unroll
            for (int mt = 0; mt < 4; mt++)
                #pragma unroll
                for (int nt = 0; nt < 4; nt++) {
                    asm volatile(
                        "mma.sync.aligned.m16n8k16.row.col.f32.bf16.bf16.f32 "
                        "{%0,%1,%2,%3}, {%4,%5,%6,%7}, {%8,%9}, {%0,%1,%2,%3};"
                        : "+f"(c[mt][nt][0]), "+f"(c[mt][nt][1]),
                          "+f"(c[mt][nt][2]), "+f"(c[mt][nt][3])
                        : "r"(a[mt][0]), "r"(a[mt][1]), "r"(a[mt][2]), "r"(a[mt][3]),
                          "r"(b[nt >> 1][(nt & 1) * 2]), "r"(b[nt >> 1][(nt & 1) * 2 + 1]));
                }
        }
    };

    issue(0); issue(1); issue(2);
    for (int kb = 0; kb < 8; kb++) {
        if (kb < 6)       asm volatile("cp.async.wait_group 2;");
        else if (kb == 6) asm volatile("cp.async.wait_group 1;");
        else              asm volatile("cp.async.wait_group 0;");
        __syncthreads();
        if (kb + 3 < 8) issue(kb + 3);
        compute(kb & (NST - 1));
    }
    __syncthreads();

    // ---- store P (bf16) into [0,32KB): 128 rows x 256B, swizzled ----
    #pragma unroll
    for (int mt = 0; mt < 4; mt++)
        #pragma unroll
        for (int half = 0; half < 2; half++) {
            const int x = mw + mt * 16 + (lane >> 2) + half * 8;
            #pragma unroll
            for (int nt = 0; nt < 4; nt++) {
                const int eloc = nw + nt * 8 + (lane & 3) * 2;
                const int ch = eloc >> 3;
                const int swz = (ch & 8) | ((ch ^ (x & 7)) & 7);
                __nv_bfloat162 hv;
                hv.x = __float2bfloat16(c[mt][nt][half * 2 + 0]);
                hv.y = __float2bfloat16(c[mt][nt][half * 2 + 1]);
                *reinterpret_cast<__nv_bfloat162*>(
                    smem + x * 256 + swz * 16 + (lane & 3) * 4) = hv;
            }
        }

    // ---- load clsB (128 rows x 128 e-cols) into [32K,64K) ----
    #pragma unroll
    for (int i = 0; i < 8; i++) {
        const int idx = i * 256 + tid;
        const int row = idx >> 4, ch = idx & 15;
        const int swz = (ch & 8) | ((ch ^ (row & 7)) & 7);
        const __nv_bfloat16* g = g_A + (size_t)(q * 128 + row) * 1024 + n0e + ch * 8;
        asm volatile("cp.async.cg.shared.global [%0], [%1], 16;"
                     :: "r"(base + 32768u + (uint32_t)(row * 256 + swz * 16)), "l"(g));
    }
    asm volatile("cp.async.commit_group;");
    asm volatile("cp.async.wait_group 0;");
    __syncthreads();

    // ---- S-MMA per batch (warp w = e-chunk w), reduce, write g_part ----
    float* __restrict__ S8 = reinterpret_cast<float*>(smem + 65536);
    const uint32_t clsB = base + 32768u;
    #pragma unroll
    for (int bi = 0; bi < 4; bi++) {
        uint32_t as[2][4], bs[2][4];
        #pragma unroll
        for (int mtl = 0; mtl < 2; mtl++) {
            const int row = bi * 32 + mtl * 16 + ((lj & 1) << 3) + li;
            const int ch = warp * 2 + (lj >> 1);
            const int swz = (ch & 8) | ((ch ^ (row & 7)) & 7);
            asm volatile("ldmatrix.sync.aligned.m8n8.x4.shared.b16 "
                         "{%0,%1,%2,%3}, [%4];"
                         : "=r"(as[mtl][0]), "=r"(as[mtl][1]),
                           "=r"(as[mtl][2]), "=r"(as[mtl][3])
                         : "r"(base + (uint32_t)(row * 256 + swz * 16)));
        }
        #pragma unroll
        for (int nh2 = 0; nh2 < 2; nh2++) {
            const int row = bi * 32 + nh2 * 16 + ((lj >> 1) << 3) + li;
            const int ch = warp * 2 + (lj & 1);
            const int swz = (ch & 8) | ((ch ^ (row & 7)) & 7);
            asm volatile("ldmatrix.sync.aligned.m8n8.x4.shared.b16 "
                         "{%0,%1,%2,%3}, [%4];"
                         : "=r"(bs[nh2][0]), "=r"(bs[nh2][1]),
                           "=r"(bs[nh2][2]), "=r"(bs[nh2][3])
                         : "r"(clsB + (uint32_t)(row * 256 + swz * 16)));
        }
        float cs[2][4][4];
        #pragma unroll
        for (int i = 0; i < 2; i++)
            #pragma unroll
            for (int j = 0; j < 4; j++)
                #pragma unroll
                for (int r = 0; r < 4; r++) cs[i][j][r] = 0.f;
        #pragma unroll
        for (int mtl = 0; mtl < 2; mtl++)
            #pragma unroll
            for (int ntl = 0; ntl < 4; ntl++) {
                asm volatile(
                    "mma.sync.aligned.m16n8k16.row.col.f32.bf16.bf16.f32 "
                    "{%0,%1,%2,%3}, {%4,%5,%6,%7}, {%8,%9}, {%0,%1,%2,%3};"
                    : "+f"(cs[mtl][ntl][0]), "+f"(cs[mtl][ntl][1]),
                      "+f"(cs[mtl][ntl][2]), "+f"(cs[mtl][ntl][3])
                    : "r"(as[mtl][0]), "r"(as[mtl][1]), "r"(as[mtl][2]), "r"(as[mtl][3]),
                      "r"(bs[ntl >> 1][(ntl & 1) * 2]), "r"(bs[ntl >> 1][(ntl & 1) * 2 + 1]));
            }
        // store warp partial 32x32 into S8[warp]
        #pragma unroll
        for (int mtl = 0; mtl < 2; mtl++)
            #pragma unroll
            for (int half = 0; half < 2; half++) {
                const int xl = mtl * 16 + (lane >> 2) + half * 8;
                #pragma unroll
                for (int ntl = 0; ntl < 4; ntl++) {
                    const int y = ntl * 8 + (lane & 3) * 2;
                    float2 v;
                    v.x = cs[mtl][ntl][half * 2 + 0];
                    v.y = cs[mtl][ntl][half * 2 + 1];
                    *reinterpret_cast<float2*>(&S8[warp * 1024 + xl * 32 + y]) = v;
                }
            }
        __syncthreads();
        #pragma unroll
        for (int t = 0; t < 4; t++) {
            const int idx = tid + t * 256;   // 0..1023
            float s = 0.f;
            #pragma unroll
            for (int w8 = 0; w8 < 8; w8++) s += S8[w8 * 1024 + idx];
            g_part[(size_t)(q * 4 + bi) * 16384 + (slice * 2 + ks) * 1024 + idx] = s;
        }
        __syncthreads();
    }

    // ---- per-batch completion ----
    __shared__ int lastF[4];
    if (tid == 0) {
        __threadfence();
        #pragma unroll
        for (int bi = 0; bi < 4; bi++)
            lastF[bi] = (atomicAdd(&g_bctr[q * 4 + bi], 1) == 15);
    }
    __syncthreads();

    __shared__ float Sf[1024];
    __shared__ float mrow[32], tv[32], rv[32], lg[32], scal[2];
    #pragma unroll
    for (int bi = 0; bi < 4; bi++) {
        if (!lastF[bi]) continue;
        const int b = q * 4 + bi;
        if (tid == 0) __threadfence();
        __syncthreads();
        #pragma unroll
        for (int t = 0; t < 4; t++) {
            const int idx = tid + t * 256;
            float s = 0.f;
            #pragma unroll
            for (int sl = 0; sl < 16; sl++)
                s += g_part[(size_t)b * 16384 + sl * 1024 + idx];
            Sf[idx] = s;
        }
        if (tid < 32) mrow[tid] = (float)mask[b * 32 + tid];
        __syncthreads();
        #pragma unroll
        for (int xi = 0; xi < 4; xi++) {
            const int x = warp * 4 + xi;
            const __nv_bfloat16* __restrict__ crow = g_A + (size_t)(b * 32 + x) * 1024;
            float ta = 0.f, ra = 0.f;
            #pragma unroll
            for (int j = 0; j < 32; j++) {
                const int d = lane + j * 32;
                const float cv = __bfloat162float(crow[d]);
                ta = fmaf(cv, g_u[d], ta);
                ra = fmaf(cv, g_v[d], ra);
            }
            #pragma unroll
            for (int o = 16; o > 0; o >>= 1) {
                ta += __shfl_xor_sync(0xFFFFFFFFu, ta, o);
                ra += __shfl_xor_sync(0xFFFFFFFFu, ra, o);
            }
            if (lane == 0) { tv[x] = ta; rv[x] = ra; }
        }
        __syncthreads();
        if (warp == 0) {
            float R = mrow[lane] * rv[lane];
            float cA = mrow[lane];
            #pragma unroll
            for (int o = 16; o > 0; o >>= 1) {
                R += __shfl_xor_sync(0xFFFFFFFFu, R, o);
                cA += __shfl_xor_sync(0xFFFFFFFFu, cA, o);
            }
            if (lane == 0) { scal[0] = R; scal[1] = cA; }
        }
        __syncthreads();
        const float R = scal[0], cA = scal[1], c0 = g_c0;
        #pragma unroll
        for (int xi = 0; xi < 4; xi++) {
            const int x = warp * 4 + xi;
            float s = mrow[lane] * Sf[x * 32 + lane];
            #pragma unroll
            for (int o = 16; o > 0; o >>= 1)
                s += __shfl_xor_sync(0xFFFFFFFFu, s, o);
            if (lane == 0)
                lg[x] = (mrow[x] != 0.f)
                    ? (s - Sf[x * 33] + tv[x] * (cA - 1.f) + (R - rv[x]) + c0 * (cA - 1.f))
                    : -100000.0f;
        }
        __syncthreads();
        if (warp == 0) {
            float v = lg[lane];
            float mx = v;
            #pragma unroll
            for (int o = 16; o > 0; o >>= 1)
                mx = fmaxf(mx, __shfl_xor_sync(0xFFFFFFFFu, mx, o));
            const float e = expf(v - mx);
            float sum = e;
            #pragma unroll
            for (int o = 16; o > 0; o >>= 1)
                sum += __shfl_xor_sync(0xFFFFFFFFu, sum, o);
            out[b * 32 + lane] = e / sum;
        }
        if (tid == 0) g_bctr[b] = 0;
        __syncthreads();
    }
}

extern "C" void kernel_launch(void* const* d_in, const int* in_sizes, int n_in,
                              void* d_out, int out_size) {
    const float* enc  = (const float*)d_in[0];
    const int*   mask = (const int*)  d_in[1];
    const float* wq   = (const float*)d_in[2];
    const float* bq   = (const float*)d_in[3];
    const float* wk   = (const float*)d_in[4];
    const float* bk   = (const float*)d_in[5];
    float* out = (float*)d_out;

    cudaFuncSetAttribute(k2_mt_gemm, cudaFuncAttributeMaxDynamicSharedMemorySize,
                         NST * STG2);
    cudaFuncSetAttribute(k3_fused, cudaFuncAttributeMaxDynamicSharedMemorySize,
                         K3_SMEM);

    k1_convert<<<385, 256>>>(enc, wq, wk, bq, bk);
    k2_mt_gemm<<<dim3(8, 8, 2), 256, NST * STG2>>>();
    k3_fused<<<dim3(8, 8, 2), 256, K3_SMEM>>>(mask, out);
}